// round 1
// baseline (speedup 1.0000x reference)
#include <cuda_runtime.h>

// ---------------- problem constants ----------------
#define EDGE_DIM 32
#define MID      64
#define NCIN     32
#define NCOUT    32
#define NF       3
#define MO       3
#define QDIM     96      // NCIN * NF
#define RADW     3072    // NCOUT * QDIM
#define EMAX     32768

// scratch for MLP output h (E x 64)
__device__ float g_h[EMAX * MID];

// ---------------- helpers ----------------
__device__ __forceinline__ float gelu_exact(float x) {
    return 0.5f * x * (1.0f + erff(x * 0.70710678118654752440f));
}

__device__ __forceinline__ float warp_allreduce_sum(float v) {
    v += __shfl_xor_sync(0xffffffffu, v, 16);
    v += __shfl_xor_sync(0xffffffffu, v, 8);
    v += __shfl_xor_sync(0xffffffffu, v, 4);
    v += __shfl_xor_sync(0xffffffffu, v, 2);
    v += __shfl_xor_sync(0xffffffffu, v, 1);
    return v;
}

__device__ __forceinline__ unsigned long long fma2(unsigned long long a,
                                                   unsigned long long b,
                                                   unsigned long long c) {
    unsigned long long d;
    asm("fma.rn.f32x2 %0, %1, %2, %3;" : "=l"(d) : "l"(a), "l"(b), "l"(c));
    return d;
}

__device__ __forceinline__ unsigned long long pack_dup(float x) {
    unsigned long long d;
    asm("mov.b64 %0, {%1, %1};" : "=l"(d) : "r"(__float_as_uint(x)));
    return d;
}

__device__ __forceinline__ void unpack2(unsigned long long v, float& lo, float& hi) {
    unsigned int a, b;
    asm("mov.b64 {%0, %1}, %2;" : "=r"(a), "=r"(b) : "l"(v));
    lo = __uint_as_float(a);
    hi = __uint_as_float(b);
}

// ---------------- Kernel A: radial MLP (edges -> h), warp per edge ----------------
__global__ void __launch_bounds__(256) mlp_kernel(
    const float* __restrict__ edges,
    const float* __restrict__ W1, const float* __restrict__ b1,
    const float* __restrict__ g1, const float* __restrict__ be1,
    const float* __restrict__ W2, const float* __restrict__ b2,
    const float* __restrict__ g2, const float* __restrict__ be2,
    int E)
{
    __shared__ float W1s[EDGE_DIM * MID];   // 2048
    __shared__ float W2s[MID * MID];        // 4096
    __shared__ float prm[6 * MID];          // b1,g1,be1,b2,g2,be2

    const int tid = threadIdx.x;
    for (int i = tid; i < EDGE_DIM * MID; i += 256) W1s[i] = W1[i];
    for (int i = tid; i < MID * MID; i += 256)      W2s[i] = W2[i];
    if (tid < MID) {
        prm[tid]           = b1[tid];
        prm[MID + tid]     = g1[tid];
        prm[2 * MID + tid] = be1[tid];
        prm[3 * MID + tid] = b2[tid];
        prm[4 * MID + tid] = g2[tid];
        prm[5 * MID + tid] = be2[tid];
    }
    __syncthreads();

    const int warp = tid >> 5;
    const int lane = tid & 31;

    for (int it = 0; it < 8; it++) {
        const int e = blockIdx.x * 64 + warp * 8 + it;
        if (e >= E) break;

        const float xv = edges[e * EDGE_DIM + lane];

        // layer 1: (32) @ (32x64); lane owns outputs j=lane and j=lane+32
        float a0 = prm[lane], a1 = prm[lane + 32];
        #pragma unroll
        for (int k = 0; k < 32; k++) {
            const float xk = __shfl_sync(0xffffffffu, xv, k);
            a0 = fmaf(xk, W1s[k * MID + lane], a0);
            a1 = fmaf(xk, W1s[k * MID + lane + 32], a1);
        }
        // LayerNorm over 64
        float mean = warp_allreduce_sum(a0 + a1) * (1.0f / 64.0f);
        float d0 = a0 - mean, d1 = a1 - mean;
        float var = warp_allreduce_sum(d0 * d0 + d1 * d1) * (1.0f / 64.0f);
        float inv = rsqrtf(var + 1e-5f);
        a0 = gelu_exact(d0 * inv * prm[MID + lane]      + prm[2 * MID + lane]);
        a1 = gelu_exact(d1 * inv * prm[MID + lane + 32] + prm[2 * MID + lane + 32]);

        // layer 2: (64) @ (64x64)
        float c0 = prm[3 * MID + lane], c1 = prm[3 * MID + lane + 32];
        #pragma unroll
        for (int k = 0; k < 32; k++) {
            const float u = __shfl_sync(0xffffffffu, a0, k);
            const float w = __shfl_sync(0xffffffffu, a1, k);
            c0 = fmaf(u, W2s[k * MID + lane], c0);
            c0 = fmaf(w, W2s[(k + 32) * MID + lane], c0);
            c1 = fmaf(u, W2s[k * MID + lane + 32], c1);
            c1 = fmaf(w, W2s[(k + 32) * MID + lane + 32], c1);
        }
        mean = warp_allreduce_sum(c0 + c1) * (1.0f / 64.0f);
        d0 = c0 - mean; d1 = c1 - mean;
        var = warp_allreduce_sum(d0 * d0 + d1 * d1) * (1.0f / 64.0f);
        inv = rsqrtf(var + 1e-5f);
        c0 = gelu_exact(d0 * inv * prm[4 * MID + lane]      + prm[5 * MID + lane]);
        c1 = gelu_exact(d1 * inv * prm[4 * MID + lane + 32] + prm[5 * MID + lane + 32]);

        g_h[e * MID + lane]      = c0;
        g_h[e * MID + lane + 32] = c1;
    }
}

// ---------------- Kernel C: fused (h @ W3) + (rw @ T) ----------------
// CTA: TE=64 edges, 512 threads = 64 edges x 8 q-parts (12 q each).
// smem: W3 double buffer [2][64][96], h tile [64][64], T tile [64][96][3]
#define TE 64
#define THREADS_C 512
#define W3SLICE (MID * QDIM)        // 6144 floats per o
#define SMEM_FLOATS (2 * W3SLICE + TE * MID + TE * QDIM * MO)  // 34816
#define SMEM_BYTES (SMEM_FLOATS * 4)                           // 139264

__global__ void __launch_bounds__(THREADS_C, 1) pair_main_kernel(
    const float* __restrict__ feats,
    const float* __restrict__ basis,
    const float* __restrict__ W3,
    float* __restrict__ out,
    int E)
{
    extern __shared__ __align__(16) float sm[];
    float* W3s = sm;                       // 2 * 6144
    float* hs  = sm + 2 * W3SLICE;         // 4096
    float* Ts  = sm + 2 * W3SLICE + TE * MID;  // 18432

    const int tid = threadIdx.x;
    const long E0 = (long)blockIdx.x * TE;

    // load h tile (coalesced)
    #pragma unroll
    for (int idx = tid; idx < TE * MID; idx += THREADS_C)
        hs[idx] = g_h[E0 * MID + idx];

    // compute T tile: T[e][q][m] = sum_mi feats[e][i][mi] * basis[e][mi][f*3+m], q=i*3+f
    for (int idx = tid; idx < TE * QDIM; idx += THREADS_C) {
        const int e = idx / QDIM, q = idx % QDIM;
        const int i = q / 3, f = q % 3;
        const float* fp = feats + (E0 + e) * (NCIN * 3) + i * 3;
        const float* bp = basis + (E0 + e) * 27 + f * 3;
        const float f0 = fp[0], f1 = fp[1], f2 = fp[2];
        float* tp = Ts + e * (QDIM * MO) + q * 3;
        #pragma unroll
        for (int m = 0; m < 3; m++)
            tp[m] = f0 * bp[m] + f1 * bp[9 + m] + f2 * bp[18 + m];
    }

    const int e = tid >> 3;     // edge within tile
    const int p = tid & 7;      // q-part
    const int q0 = p * 12;

    // precompute W3 gather offsets for this thread (c*3072 + q), 12 elements
    int wofs[12];
    #pragma unroll
    for (int k = 0; k < 12; k++) {
        const int idx = k * THREADS_C + tid;       // = c*96 + q
        wofs[k] = (idx / QDIM) * RADW + (idx % QDIM);
    }

    // preload o=0 slice into registers
    float wreg[12];
    #pragma unroll
    for (int k = 0; k < 12; k++) wreg[k] = W3[wofs[k]];

    const float* hrow = hs + e * MID;
    const float* Trow = Ts + e * (QDIM * MO);

    for (int o = 0; o < NCOUT; o++) {
        float* buf = W3s + (o & 1) * W3SLICE;
        // stage current slice into smem
        #pragma unroll
        for (int k = 0; k < 12; k++) buf[k * THREADS_C + tid] = wreg[k];
        __syncthreads();
        // prefetch next slice (global, overlapped with compute)
        if (o + 1 < NCOUT) {
            const int base = (o + 1) * QDIM;
            #pragma unroll
            for (int k = 0; k < 12; k++) wreg[k] = W3[wofs[k] + base];
        }

        // rw[e][o][q0..q0+11] = sum_c h[e][c] * W3[c][o*96+q]  (f32x2 packed)
        unsigned long long a0 = 0, a1 = 0, a2 = 0, a3 = 0, a4 = 0, a5 = 0;
        const ulonglong2* wq = reinterpret_cast<const ulonglong2*>(buf + q0);
        #pragma unroll 8
        for (int c = 0; c < MID; c++) {
            const unsigned long long h2 = pack_dup(hrow[c]);
            const ulonglong2 wa = wq[c * 24 + 0];
            const ulonglong2 wb = wq[c * 24 + 1];
            const ulonglong2 wc = wq[c * 24 + 2];
            a0 = fma2(h2, wa.x, a0);
            a1 = fma2(h2, wa.y, a1);
            a2 = fma2(h2, wb.x, a2);
            a3 = fma2(h2, wb.y, a3);
            a4 = fma2(h2, wc.x, a4);
            a5 = fma2(h2, wc.y, a5);
        }

        float rw[12];
        unpack2(a0, rw[0], rw[1]);
        unpack2(a1, rw[2], rw[3]);
        unpack2(a2, rw[4], rw[5]);
        unpack2(a3, rw[6], rw[7]);
        unpack2(a4, rw[8], rw[9]);
        unpack2(a5, rw[10], rw[11]);

        // out[e][o][m] += rw[q] * T[e][q][m]
        float o0 = 0.f, o1 = 0.f, o2 = 0.f;
        #pragma unroll
        for (int j = 0; j < 12; j++) {
            const float* tp = Trow + (q0 + j) * 3;
            o0 = fmaf(rw[j], tp[0], o0);
            o1 = fmaf(rw[j], tp[1], o1);
            o2 = fmaf(rw[j], tp[2], o2);
        }
        // reduce across the 8 q-parts (consecutive lanes)
        o0 += __shfl_down_sync(0xffffffffu, o0, 4, 8);
        o1 += __shfl_down_sync(0xffffffffu, o1, 4, 8);
        o2 += __shfl_down_sync(0xffffffffu, o2, 4, 8);
        o0 += __shfl_down_sync(0xffffffffu, o0, 2, 8);
        o1 += __shfl_down_sync(0xffffffffu, o1, 2, 8);
        o2 += __shfl_down_sync(0xffffffffu, o2, 2, 8);
        o0 += __shfl_down_sync(0xffffffffu, o0, 1, 8);
        o1 += __shfl_down_sync(0xffffffffu, o1, 1, 8);
        o2 += __shfl_down_sync(0xffffffffu, o2, 1, 8);

        if (p == 0) {
            float* op = out + (E0 + e) * (NCOUT * MO) + o * 3;
            op[0] = o0; op[1] = o1; op[2] = o2;
        }
        // next iteration's staging writes the other buffer; the sync at the
        // top of next iteration orders it against this iteration's reads of
        // that buffer two stages back (and wreg is already consumed: STS
        // happens before the prefetch overwrite in program order).
        __syncthreads();
    }
}

// ---------------- launch ----------------
extern "C" void kernel_launch(void* const* d_in, const int* in_sizes, int n_in,
                              void* d_out, int out_size) {
    const float* edges = (const float*)d_in[0];
    const float* feats = (const float*)d_in[1];
    const float* basis = (const float*)d_in[2];
    const float* W1    = (const float*)d_in[3];
    const float* b1    = (const float*)d_in[4];
    const float* g1    = (const float*)d_in[5];
    const float* be1   = (const float*)d_in[6];
    const float* W2    = (const float*)d_in[7];
    const float* b2    = (const float*)d_in[8];
    const float* g2    = (const float*)d_in[9];
    const float* be2   = (const float*)d_in[10];
    const float* W3    = (const float*)d_in[11];
    float* out = (float*)d_out;

    const int E = in_sizes[0] / EDGE_DIM;

    const int blocksA = (E + 63) / 64;
    mlp_kernel<<<blocksA, 256>>>(edges, W1, b1, g1, be1, W2, b2, g2, be2, E);

    cudaFuncSetAttribute(pair_main_kernel,
                         cudaFuncAttributeMaxDynamicSharedMemorySize, SMEM_BYTES);
    const int blocksC = E / TE;
    pair_main_kernel<<<blocksC, THREADS_C, SMEM_BYTES>>>(feats, basis, W3, out, E);
}

// round 5
// speedup vs baseline: 4.6377x; 4.6377x over previous
#include <cuda_runtime.h>
#include <cuda_fp16.h>
#include <cstdint>

// ---------------- problem constants ----------------
#define EDGE_DIM 32
#define MID      64
#define NCIN     32
#define NCOUT    32
#define MO       3
#define QDIM     96
#define RADW     3072
#define EMAX     32768
#define NCHUNK   32

// scratch
__device__ float  g_h[EMAX * MID];
// per chunk: hi image (96 rows x 128 B) then lo image, fragment-ready + swizzled
__device__ __half g_B[NCHUNK * 2 * QDIM * MID];

// ---------------- helpers ----------------
__device__ __forceinline__ float gelu_exact(float x) {
    return 0.5f * x * (1.0f + erff(x * 0.70710678118654752440f));
}
__device__ __forceinline__ float warp_allreduce_sum(float v) {
    v += __shfl_xor_sync(0xffffffffu, v, 16);
    v += __shfl_xor_sync(0xffffffffu, v, 8);
    v += __shfl_xor_sync(0xffffffffu, v, 4);
    v += __shfl_xor_sync(0xffffffffu, v, 2);
    v += __shfl_xor_sync(0xffffffffu, v, 1);
    return v;
}
__device__ __forceinline__ void split2(float2 p, uint32_t& hi, uint32_t& lo) {
    __half h0 = __float2half_rn(p.x), h1 = __float2half_rn(p.y);
    float  r0 = p.x - __half2float(h0), r1 = p.y - __half2float(h1);
    __half l0 = __float2half_rn(r0), l1 = __float2half_rn(r1);
    __half2 hh = __halves2half2(h0, h1), ll = __halves2half2(l0, l1);
    hi = *(uint32_t*)&hh;
    lo = *(uint32_t*)&ll;
}
__device__ __forceinline__ void mma16816(float c[4], const uint32_t a[4],
                                         uint32_t b0, uint32_t b1) {
    asm volatile(
        "mma.sync.aligned.m16n8k16.row.col.f32.f16.f16.f32 "
        "{%0,%1,%2,%3}, {%4,%5,%6,%7}, {%8,%9}, {%0,%1,%2,%3};"
        : "+f"(c[0]), "+f"(c[1]), "+f"(c[2]), "+f"(c[3])
        : "r"(a[0]), "r"(a[1]), "r"(a[2]), "r"(a[3]), "r"(b0), "r"(b1));
}

// ---------------- Kernel P: W3 -> fp16 hi/lo fragment images ----------------
// Row n (0..95 per chunk), 128 B: k-halves ordered so lane c's ld.64 at
// kt*32 + c*8 yields [2c, 2c+1, 2c+8, 2c+9] (b0 = first pair, b1 = second).
// XOR-swizzle (n&3)<<5 makes the fragment loads bank-conflict-free.
__global__ void __launch_bounds__(256) prep_w3(const float* __restrict__ W3) {
    int idx = blockIdx.x * 256 + threadIdx.x;     // over 64*3072
    if (idx >= MID * RADW) return;
    int k = idx / RADW, n = idx % RADW;
    int chunk = n / QDIM, nl = n % QDIM;
    float wv = W3[idx];
    __half h = __float2half_rn(wv);
    __half l = __float2half_rn(wv - __half2float(h));
    int kt = k >> 4, kk = k & 15;
    int cc = (kk & 7) >> 1;
    int w4 = (kk & 1) + ((kk >> 3) << 1);
    int pos = kt * 32 + cc * 8 + w4 * 2;          // byte within 128-B row
    pos ^= (nl & 3) << 5;
    int byte_hi = chunk * 24576 + nl * 128 + pos;
    g_B[byte_hi >> 1]             = h;
    g_B[(byte_hi + 12288) >> 1]   = l;
}

// ---------------- Kernel A: radial MLP (known-good from R1) ----------------
__global__ void __launch_bounds__(256) mlp_kernel(
    const float* __restrict__ edges,
    const float* __restrict__ W1, const float* __restrict__ b1,
    const float* __restrict__ g1, const float* __restrict__ be1,
    const float* __restrict__ W2, const float* __restrict__ b2,
    const float* __restrict__ g2, const float* __restrict__ be2,
    int E)
{
    __shared__ float W1s[EDGE_DIM * MID];
    __shared__ float W2s[MID * MID];
    __shared__ float prm[6 * MID];
    const int tid = threadIdx.x;
    for (int i = tid; i < EDGE_DIM * MID; i += 256) W1s[i] = W1[i];
    for (int i = tid; i < MID * MID; i += 256)      W2s[i] = W2[i];
    if (tid < MID) {
        prm[tid] = b1[tid]; prm[MID + tid] = g1[tid]; prm[2*MID + tid] = be1[tid];
        prm[3*MID + tid] = b2[tid]; prm[4*MID + tid] = g2[tid]; prm[5*MID + tid] = be2[tid];
    }
    __syncthreads();
    const int warp = tid >> 5, lane = tid & 31;
    for (int it = 0; it < 8; it++) {
        const int e = blockIdx.x * 64 + warp * 8 + it;
        if (e >= E) break;
        const float xv = edges[e * EDGE_DIM + lane];
        float a0 = prm[lane], a1 = prm[lane + 32];
        #pragma unroll
        for (int k = 0; k < 32; k++) {
            const float xk = __shfl_sync(0xffffffffu, xv, k);
            a0 = fmaf(xk, W1s[k * MID + lane], a0);
            a1 = fmaf(xk, W1s[k * MID + lane + 32], a1);
        }
        float mean = warp_allreduce_sum(a0 + a1) * (1.0f / 64.0f);
        float d0 = a0 - mean, d1 = a1 - mean;
        float var = warp_allreduce_sum(d0 * d0 + d1 * d1) * (1.0f / 64.0f);
        float inv = rsqrtf(var + 1e-5f);
        a0 = gelu_exact(d0 * inv * prm[MID + lane]      + prm[2*MID + lane]);
        a1 = gelu_exact(d1 * inv * prm[MID + lane + 32] + prm[2*MID + lane + 32]);
        float c0 = prm[3*MID + lane], c1 = prm[3*MID + lane + 32];
        #pragma unroll
        for (int k = 0; k < 32; k++) {
            const float u = __shfl_sync(0xffffffffu, a0, k);
            const float w = __shfl_sync(0xffffffffu, a1, k);
            c0 = fmaf(u, W2s[k * MID + lane], c0);
            c0 = fmaf(w, W2s[(k + 32) * MID + lane], c0);
            c1 = fmaf(u, W2s[k * MID + lane + 32], c1);
            c1 = fmaf(w, W2s[(k + 32) * MID + lane + 32], c1);
        }
        mean = warp_allreduce_sum(c0 + c1) * (1.0f / 64.0f);
        d0 = c0 - mean; d1 = c1 - mean;
        var = warp_allreduce_sum(d0 * d0 + d1 * d1) * (1.0f / 64.0f);
        inv = rsqrtf(var + 1e-5f);
        c0 = gelu_exact(d0 * inv * prm[4*MID + lane]      + prm[5*MID + lane]);
        c1 = gelu_exact(d1 * inv * prm[4*MID + lane + 32] + prm[5*MID + lane + 32]);
        g_h[e * MID + lane]      = c0;
        g_h[e * MID + lane + 32] = c1;
    }
}

// ---------------- Kernel M: mma.sync fp16x3 GEMM fused with rw@T ----------------
// 256 thr / 8 warps, 128 edges per CTA. Warp w owns edges [w*16, w*16+16),
// full n=96 per chunk o. A (h hi/lo) resident in registers.
#define SM_B    0                      // 2 x 24576 B (hi+lo chunk, double buffer)
#define SM_TS2  49152                  // float2, pitch 130 per q : 96*130*8 = 99840
#define SM_TS1  (49152 + 99840)        // float,  pitch 132 per q : 96*132*4 = 50688
#define SM_TOTAL (49152 + 99840 + 50688)   // 199680 B

__global__ void __launch_bounds__(256, 1) pair_main_kernel(
    const float* __restrict__ feats,
    const float* __restrict__ basis,
    float* __restrict__ out,
    int E)
{
    extern __shared__ __align__(1024) char smem[];
    float2* Ts2 = (float2*)(smem + SM_TS2);
    float*  Ts1 = (float*)(smem + SM_TS1);

    const int tid = threadIdx.x, w = tid >> 5, lane = tid & 31;
    const int r = lane >> 2, c = lane & 3;
    const int E0 = blockIdx.x * 128;
    const int el = w * 16 + r;          // CTA-local edge for row A (and el+8 for row B)
    const int er = E0 + el;             // global edge

    // ---- A fragments: h rows er and er+8, split fp16 hi/lo, held in regs ----
    uint32_t Ahi[4][4], Alo[4][4];
    #pragma unroll
    for (int kt = 0; kt < 4; kt++) {
        const int k0 = kt * 16 + 2 * c;
        float2 p0 = *(const float2*)(g_h + (size_t)er * MID + k0);
        float2 p1 = *(const float2*)(g_h + (size_t)er * MID + k0 + 8);
        float2 p2 = *(const float2*)(g_h + (size_t)(er + 8) * MID + k0);
        float2 p3 = *(const float2*)(g_h + (size_t)(er + 8) * MID + k0 + 8);
        split2(p0, Ahi[kt][0], Alo[kt][0]);
        split2(p2, Ahi[kt][1], Alo[kt][1]);
        split2(p1, Ahi[kt][2], Alo[kt][2]);
        split2(p3, Ahi[kt][3], Alo[kt][3]);
    }

    // ---- T tile (fp32): T[q][e] = (feats@basis)[e][q][0..2] ----
    for (int idx = tid; idx < 128 * QDIM; idx += 256) {
        const int e = idx / QDIM, q = idx - e * QDIM;
        const int i = q / 3, f = q - i * 3;
        const float* fp = feats + (size_t)(E0 + e) * (NCIN * 3) + i * 3;
        const float* bp = basis + (size_t)(E0 + e) * 27 + f * 3;
        const float f0 = fp[0], f1 = fp[1], f2 = fp[2];
        Ts2[q * 130 + e] = make_float2(f0 * bp[0] + f1 * bp[9]  + f2 * bp[18],
                                       f0 * bp[1] + f1 * bp[10] + f2 * bp[19]);
        Ts1[q * 132 + e] = f0 * bp[2] + f1 * bp[11] + f2 * bp[20];
    }

    // ---- stage chunk 0 (24576 B = 1536 float4, 6 per thread) ----
    const float4* gB4 = (const float4*)g_B;
    {
        float4* d = (float4*)(smem + SM_B);
        #pragma unroll
        for (int j = 0; j < 6; j++) d[tid + j * 256] = gB4[tid + j * 256];
    }
    __syncthreads();

    // per-lane B fragment byte offset within a chunk image, per kt
    uint32_t bk[4];
    #pragma unroll
    for (int kt = 0; kt < 4; kt++)
        bk[kt] = (uint32_t)(r * 128 + ((kt * 32 + c * 8) ^ ((r & 3) << 5)));

    for (int o = 0; o < NCHUNK; o++) {
        // prefetch next chunk into regs (overlaps MMA)
        float4 stg[6];
        if (o + 1 < NCHUNK) {
            #pragma unroll
            for (int j = 0; j < 6; j++)
                stg[j] = gB4[(size_t)(o + 1) * 1536 + tid + j * 256];
        }

        const char* buf = smem + SM_B + (o & 1) * 24576;
        float C[12][4];
        #pragma unroll
        for (int nt = 0; nt < 12; nt++) {
            C[nt][0] = 0.f; C[nt][1] = 0.f; C[nt][2] = 0.f; C[nt][3] = 0.f;
        }

        #pragma unroll
        for (int kt = 0; kt < 4; kt++) {
            uint2 bh[12], bl[12];
            #pragma unroll
            for (int nt = 0; nt < 12; nt++)
                bh[nt] = *(const uint2*)(buf + bk[kt] + nt * 1024);
            #pragma unroll
            for (int nt = 0; nt < 12; nt++)
                bl[nt] = *(const uint2*)(buf + 12288 + bk[kt] + nt * 1024);
            #pragma unroll
            for (int nt = 0; nt < 12; nt++) {
                mma16816(C[nt], Ahi[kt], bh[nt].x, bh[nt].y);   // hi*hi
                mma16816(C[nt], Ahi[kt], bl[nt].x, bl[nt].y);   // hi*lo
                mma16816(C[nt], Alo[kt], bh[nt].x, bh[nt].y);   // lo*hi
            }
        }

        // ---- epilogue: out[e][o][m] = sum_q C[e][q] * T[e][q][m] ----
        float a0 = 0.f, a1 = 0.f, a2 = 0.f;     // edge el  (row er)
        float b0 = 0.f, b1 = 0.f, b2 = 0.f;     // edge el+8 (row er+8)
        #pragma unroll
        for (int nt = 0; nt < 12; nt++) {
            const int q0 = nt * 8 + 2 * c;
            const float2 tA0 = Ts2[q0 * 130 + el];
            const float2 tA1 = Ts2[(q0 + 1) * 130 + el];
            const float  sA0 = Ts1[q0 * 132 + el];
            const float  sA1 = Ts1[(q0 + 1) * 132 + el];
            const float2 tB0 = Ts2[q0 * 130 + el + 8];
            const float2 tB1 = Ts2[(q0 + 1) * 130 + el + 8];
            const float  sB0 = Ts1[q0 * 132 + el + 8];
            const float  sB1 = Ts1[(q0 + 1) * 132 + el + 8];
            a0 += C[nt][0] * tA0.x + C[nt][1] * tA1.x;
            a1 += C[nt][0] * tA0.y + C[nt][1] * tA1.y;
            a2 += C[nt][0] * sA0   + C[nt][1] * sA1;
            b0 += C[nt][2] * tB0.x + C[nt][3] * tB1.x;
            b1 += C[nt][2] * tB0.y + C[nt][3] * tB1.y;
            b2 += C[nt][2] * sB0   + C[nt][3] * sB1;
        }
        a0 += __shfl_xor_sync(0xffffffffu, a0, 1);
        a1 += __shfl_xor_sync(0xffffffffu, a1, 1);
        a2 += __shfl_xor_sync(0xffffffffu, a2, 1);
        b0 += __shfl_xor_sync(0xffffffffu, b0, 1);
        b1 += __shfl_xor_sync(0xffffffffu, b1, 1);
        b2 += __shfl_xor_sync(0xffffffffu, b2, 1);
        a0 += __shfl_xor_sync(0xffffffffu, a0, 2);
        a1 += __shfl_xor_sync(0xffffffffu, a1, 2);
        a2 += __shfl_xor_sync(0xffffffffu, a2, 2);
        b0 += __shfl_xor_sync(0xffffffffu, b0, 2);
        b1 += __shfl_xor_sync(0xffffffffu, b1, 2);
        b2 += __shfl_xor_sync(0xffffffffu, b2, 2);

        if (c == 0) {
            float* op = out + (size_t)er * (NCOUT * MO) + o * 3;
            op[0] = a0; op[1] = a1; op[2] = a2;
            float* op2 = out + (size_t)(er + 8) * (NCOUT * MO) + o * 3;
            op2[0] = b0; op2[1] = b1; op2[2] = b2;
        }

        // store staged chunk (other buffer; last read of it ended at o-1's sync)
        if (o + 1 < NCHUNK) {
            float4* d = (float4*)(smem + SM_B + ((o + 1) & 1) * 24576);
            #pragma unroll
            for (int j = 0; j < 6; j++) d[tid + j * 256] = stg[j];
        }
        __syncthreads();
    }
}

// ---------------- launch ----------------
extern "C" void kernel_launch(void* const* d_in, const int* in_sizes, int n_in,
                              void* d_out, int out_size) {
    const float* edges = (const float*)d_in[0];
    const float* feats = (const float*)d_in[1];
    const float* basis = (const float*)d_in[2];
    const float* W1    = (const float*)d_in[3];
    const float* b1    = (const float*)d_in[4];
    const float* g1    = (const float*)d_in[5];
    const float* be1   = (const float*)d_in[6];
    const float* W2    = (const float*)d_in[7];
    const float* b2    = (const float*)d_in[8];
    const float* g2    = (const float*)d_in[9];
    const float* be2   = (const float*)d_in[10];
    const float* W3    = (const float*)d_in[11];
    float* out = (float*)d_out;

    const int E = in_sizes[0] / EDGE_DIM;

    prep_w3<<<(MID * RADW + 255) / 256, 256>>>(W3);
    mlp_kernel<<<(E + 63) / 64, 256>>>(edges, W1, b1, g1, be1, W2, b2, g2, be2, E);

    cudaFuncSetAttribute(pair_main_kernel,
                         cudaFuncAttributeMaxDynamicSharedMemorySize, SM_TOTAL);
    pair_main_kernel<<<E / 128, 256, SM_TOTAL>>>(feats, basis, out, E);
}

// round 6
// speedup vs baseline: 4.8109x; 1.0374x over previous
#include <cuda_runtime.h>
#include <cuda_fp16.h>
#include <cstdint>

// ---------------- problem constants ----------------
#define EDGE_DIM 32
#define MID      64
#define NCIN     32
#define NCOUT    32
#define MO       3
#define QDIM     96
#define RADW     3072
#define EMAX     32768
#define NCHUNK   32

// scratch
__device__ float  g_h[EMAX * MID];
// per chunk 24576 B: [ng(2)][hi/lo][j(12)][lane(32) x 16B] fragment-register-order
__device__ __half g_B[NCHUNK * 24576 / 2];

// ---------------- helpers ----------------
__device__ __forceinline__ float gelu_exact(float x) {
    return 0.5f * x * (1.0f + erff(x * 0.70710678118654752440f));
}
__device__ __forceinline__ float warp_allreduce_sum(float v) {
    v += __shfl_xor_sync(0xffffffffu, v, 16);
    v += __shfl_xor_sync(0xffffffffu, v, 8);
    v += __shfl_xor_sync(0xffffffffu, v, 4);
    v += __shfl_xor_sync(0xffffffffu, v, 2);
    v += __shfl_xor_sync(0xffffffffu, v, 1);
    return v;
}
__device__ __forceinline__ void split2(float2 p, uint32_t& hi, uint32_t& lo) {
    __half h0 = __float2half_rn(p.x), h1 = __float2half_rn(p.y);
    float  r0 = p.x - __half2float(h0), r1 = p.y - __half2float(h1);
    __half l0 = __float2half_rn(r0), l1 = __float2half_rn(r1);
    __half2 hh = __halves2half2(h0, h1), ll = __halves2half2(l0, l1);
    hi = *(uint32_t*)&hh;
    lo = *(uint32_t*)&ll;
}
__device__ __forceinline__ void mma16816(float c[4], const uint32_t a[4],
                                         uint32_t b0, uint32_t b1) {
    asm volatile(
        "mma.sync.aligned.m16n8k16.row.col.f32.f16.f16.f32 "
        "{%0,%1,%2,%3}, {%4,%5,%6,%7}, {%8,%9}, {%0,%1,%2,%3};"
        : "+f"(c[0]), "+f"(c[1]), "+f"(c[2]), "+f"(c[3])
        : "r"(a[0]), "r"(a[1]), "r"(a[2]), "r"(a[3]), "r"(b0), "r"(b1));
}

// ---------------- Kernel P: W3 -> fragment-register-order fp16 hi/lo images ----
// Lane (r,c)=(rr*4+cc) holds, per uint4 load j (= kt*3 + nth), regs:
//   x = frag(nt=2nth)   b0,  y = b1,  z = frag(nt=2nth+1) b0,  w = b1
// where b0 = halves B[kt*16+2c, n] B[kt*16+2c+1, n], b1 = +8 in k, n = rr.
__global__ void __launch_bounds__(256) prep_w3(const float* __restrict__ W3) {
    int idx = blockIdx.x * 256 + threadIdx.x;     // over 64*3072
    if (idx >= MID * RADW) return;
    int k = idx / RADW, n = idx % RADW;
    int chunk = n / QDIM, nl = n % QDIM;
    int ng = nl / 48, nq = nl % 48;
    int nt = nq >> 3, rr = nq & 7;
    int kt = k >> 4, kk = k & 15;
    int cc = (kk >> 1) & 3, bb = kk >> 3, hp = kk & 1;
    int lane = rr * 4 + cc;
    int j = kt * 3 + (nt >> 1);
    int r4 = ((nt & 1) << 1) + bb;
    int off = chunk * 24576 + ng * 12288 + j * 512 + lane * 16 + r4 * 4 + hp * 2;

    float wv = W3[idx];
    __half h = __float2half_rn(wv);
    __half l = __float2half_rn(wv - __half2float(h));
    g_B[off >> 1]          = h;
    g_B[(off + 6144) >> 1] = l;
}

// ---------------- Kernel A: radial MLP (known-good) ----------------
__global__ void __launch_bounds__(256) mlp_kernel(
    const float* __restrict__ edges,
    const float* __restrict__ W1, const float* __restrict__ b1,
    const float* __restrict__ g1, const float* __restrict__ be1,
    const float* __restrict__ W2, const float* __restrict__ b2,
    const float* __restrict__ g2, const float* __restrict__ be2,
    int E)
{
    __shared__ float W1s[EDGE_DIM * MID];
    __shared__ float W2s[MID * MID];
    __shared__ float prm[6 * MID];
    const int tid = threadIdx.x;
    for (int i = tid; i < EDGE_DIM * MID; i += 256) W1s[i] = W1[i];
    for (int i = tid; i < MID * MID; i += 256)      W2s[i] = W2[i];
    if (tid < MID) {
        prm[tid] = b1[tid]; prm[MID + tid] = g1[tid]; prm[2*MID + tid] = be1[tid];
        prm[3*MID + tid] = b2[tid]; prm[4*MID + tid] = g2[tid]; prm[5*MID + tid] = be2[tid];
    }
    __syncthreads();
    const int warp = tid >> 5, lane = tid & 31;
    for (int it = 0; it < 8; it++) {
        const int e = blockIdx.x * 64 + warp * 8 + it;
        if (e >= E) break;
        const float xv = edges[e * EDGE_DIM + lane];
        float a0 = prm[lane], a1 = prm[lane + 32];
        #pragma unroll
        for (int k = 0; k < 32; k++) {
            const float xk = __shfl_sync(0xffffffffu, xv, k);
            a0 = fmaf(xk, W1s[k * MID + lane], a0);
            a1 = fmaf(xk, W1s[k * MID + lane + 32], a1);
        }
        float mean = warp_allreduce_sum(a0 + a1) * (1.0f / 64.0f);
        float d0 = a0 - mean, d1 = a1 - mean;
        float var = warp_allreduce_sum(d0 * d0 + d1 * d1) * (1.0f / 64.0f);
        float inv = rsqrtf(var + 1e-5f);
        a0 = gelu_exact(d0 * inv * prm[MID + lane]      + prm[2*MID + lane]);
        a1 = gelu_exact(d1 * inv * prm[MID + lane + 32] + prm[2*MID + lane + 32]);
        float c0 = prm[3*MID + lane], c1 = prm[3*MID + lane + 32];
        #pragma unroll
        for (int k = 0; k < 32; k++) {
            const float u = __shfl_sync(0xffffffffu, a0, k);
            const float w = __shfl_sync(0xffffffffu, a1, k);
            c0 = fmaf(u, W2s[k * MID + lane], c0);
            c0 = fmaf(w, W2s[(k + 32) * MID + lane], c0);
            c1 = fmaf(u, W2s[k * MID + lane + 32], c1);
            c1 = fmaf(w, W2s[(k + 32) * MID + lane + 32], c1);
        }
        mean = warp_allreduce_sum(c0 + c1) * (1.0f / 64.0f);
        d0 = c0 - mean; d1 = c1 - mean;
        var = warp_allreduce_sum(d0 * d0 + d1 * d1) * (1.0f / 64.0f);
        inv = rsqrtf(var + 1e-5f);
        c0 = gelu_exact(d0 * inv * prm[4*MID + lane]      + prm[5*MID + lane]);
        c1 = gelu_exact(d1 * inv * prm[4*MID + lane + 32] + prm[5*MID + lane + 32]);
        g_h[e * MID + lane]      = c0;
        g_h[e * MID + lane + 32] = c1;
    }
}

// ---------------- Kernel M: mma.sync fp16x3, warp = 32 edges x 48 n ----------------
// 256 thr / 8 warps = 4 edge-groups x 2 n-halves; 128 edges per CTA.
#define SM_B     0                     // 2 x 24576
#define SM_T     49152                 // 128 edges x 832 B (48 qp x uint4, pitch 832)
#define SM_PED   (49152 + 128*832)     // 2 parity x 4 eg x 8 r x 12 floats = 3072 B
#define SM_TOTAL (SM_PED + 3072)       // 158720

__global__ void __launch_bounds__(256, 1) pair_main_kernel(
    const float* __restrict__ feats,
    const float* __restrict__ basis,
    float* __restrict__ out,
    int E)
{
    extern __shared__ __align__(1024) char smem[];
    const int tid = threadIdx.x, w = tid >> 5, lane = tid & 31;
    const int r = lane >> 2, c = lane & 3;
    const int eg = w >> 1, ng = w & 1;
    const int E0 = blockIdx.x * 128;
    const int ebase = eg * 32 + r;          // local edge of slot 0

    // ---- A fragments: 4 edge rows (ebase + 8s), fp16 hi/lo, resident ----
    uint32_t Ahi[2][4][4], Alo[2][4][4];
    #pragma unroll
    for (int mt = 0; mt < 2; mt++) {
        const size_t e0 = (size_t)(E0 + ebase + mt * 16) * MID;
        const size_t e1 = e0 + 8 * MID;
        #pragma unroll
        for (int kt = 0; kt < 4; kt++) {
            const int k0 = kt * 16 + 2 * c;
            float2 p0 = *(const float2*)(g_h + e0 + k0);
            float2 p1 = *(const float2*)(g_h + e0 + k0 + 8);
            float2 p2 = *(const float2*)(g_h + e1 + k0);
            float2 p3 = *(const float2*)(g_h + e1 + k0 + 8);
            split2(p0, Ahi[mt][kt][0], Alo[mt][kt][0]);
            split2(p2, Ahi[mt][kt][1], Alo[mt][kt][1]);
            split2(p1, Ahi[mt][kt][2], Alo[mt][kt][2]);
            split2(p3, Ahi[mt][kt][3], Alo[mt][kt][3]);
        }
    }

    // ---- T tile: per (e, qp) one uint4 = fp16 {t0[0],t0[1], t0[2],_, t1[0],t1[1], t1[2],_}
    for (int idx = tid; idx < 128 * 48; idx += 256) {
        const int e = idx / 48, qp = idx % 48;
        const int q0 = 2 * qp, q1 = q0 + 1;
        const int i0 = q0 / 3, f0 = q0 % 3, i1 = q1 / 3, f1 = q1 % 3;
        const float* fe = feats + (size_t)(E0 + e) * (NCIN * 3);
        const float* be = basis + (size_t)(E0 + e) * 27;
        const float a0 = fe[i0*3], a1 = fe[i0*3+1], a2 = fe[i0*3+2];
        const float b0 = fe[i1*3], b1 = fe[i1*3+1], b2 = fe[i1*3+2];
        float t0[3], t1[3];
        #pragma unroll
        for (int m = 0; m < 3; m++) {
            t0[m] = a0 * be[f0*3+m] + a1 * be[9 + f0*3+m] + a2 * be[18 + f0*3+m];
            t1[m] = b0 * be[f1*3+m] + b1 * be[9 + f1*3+m] + b2 * be[18 + f1*3+m];
        }
        half2 hx = __floats2half2_rn(t0[0], t0[1]);
        half2 hy = __floats2half2_rn(t0[2], 0.0f);
        half2 hz = __floats2half2_rn(t1[0], t1[1]);
        half2 hw = __floats2half2_rn(t1[2], 0.0f);
        uint4 v;
        v.x = *(uint32_t*)&hx; v.y = *(uint32_t*)&hy;
        v.z = *(uint32_t*)&hz; v.w = *(uint32_t*)&hw;
        *(uint4*)(smem + SM_T + e * 832 + qp * 16) = v;
    }

    // ---- stage chunk 0 ----
    const float4* gB4 = (const float4*)g_B;
    {
        float4* d = (float4*)(smem + SM_B);
        #pragma unroll
        for (int j = 0; j < 6; j++) d[tid + j * 256] = gB4[tid + j * 256];
    }
    __syncthreads();

    float* ped = (float*)(smem + SM_PED);

    for (int o = 0; o < NCHUNK; o++) {
        // prefetch next chunk
        float4 stg[6];
        if (o + 1 < NCHUNK) {
            #pragma unroll
            for (int j = 0; j < 6; j++)
                stg[j] = gB4[(size_t)(o + 1) * 1536 + tid + j * 256];
        }

        const char* buf = smem + SM_B + (o & 1) * 24576 + ng * 12288;
        float C[2][6][4];
        #pragma unroll
        for (int mt = 0; mt < 2; mt++)
            #pragma unroll
            for (int nt = 0; nt < 6; nt++) {
                C[mt][nt][0] = 0.f; C[mt][nt][1] = 0.f;
                C[mt][nt][2] = 0.f; C[mt][nt][3] = 0.f;
            }

        #pragma unroll
        for (int kt = 0; kt < 4; kt++) {
            uint4 bh[3], bl[3];
            #pragma unroll
            for (int jj = 0; jj < 3; jj++) {
                bh[jj] = *(const uint4*)(buf + (kt*3 + jj) * 512 + lane * 16);
                bl[jj] = *(const uint4*)(buf + 6144 + (kt*3 + jj) * 512 + lane * 16);
            }
            #pragma unroll
            for (int jj = 0; jj < 3; jj++) {
                #pragma unroll
                for (int mt = 0; mt < 2; mt++) {
                    mma16816(C[mt][2*jj],   Ahi[mt][kt], bh[jj].x, bh[jj].y);
                    mma16816(C[mt][2*jj],   Ahi[mt][kt], bl[jj].x, bl[jj].y);
                    mma16816(C[mt][2*jj],   Alo[mt][kt], bh[jj].x, bh[jj].y);
                    mma16816(C[mt][2*jj+1], Ahi[mt][kt], bh[jj].z, bh[jj].w);
                    mma16816(C[mt][2*jj+1], Ahi[mt][kt], bl[jj].z, bl[jj].w);
                    mma16816(C[mt][2*jj+1], Alo[mt][kt], bh[jj].z, bh[jj].w);
                }
            }
        }

        // ---- epilogue: acc[s][m] = sum over this warp's 48 q of C * T ----
        float acc[4][3];
        #pragma unroll
        for (int s = 0; s < 4; s++) { acc[s][0]=0.f; acc[s][1]=0.f; acc[s][2]=0.f; }

        #pragma unroll
        for (int nt = 0; nt < 6; nt++) {
            const int qp = ng * 24 + nt * 4 + c;
            #pragma unroll
            for (int s = 0; s < 4; s++) {
                const int es = ebase + 8 * s;
                uint4 tv = *(const uint4*)(smem + SM_T + es * 832 + qp * 16);
                float2 u0 = __half22float2(*(half2*)&tv.x);
                float2 u1 = __half22float2(*(half2*)&tv.y);
                float2 u2 = __half22float2(*(half2*)&tv.z);
                float2 u3 = __half22float2(*(half2*)&tv.w);
                const float cA = C[s >> 1][nt][(s & 1) * 2];
                const float cB = C[s >> 1][nt][(s & 1) * 2 + 1];
                acc[s][0] = fmaf(cA, u0.x, fmaf(cB, u2.x, acc[s][0]));
                acc[s][1] = fmaf(cA, u0.y, fmaf(cB, u2.y, acc[s][1]));
                acc[s][2] = fmaf(cA, u1.x, fmaf(cB, u3.x, acc[s][2]));
            }
        }
        #pragma unroll
        for (int s = 0; s < 4; s++) {
            #pragma unroll
            for (int m = 0; m < 3; m++) {
                acc[s][m] += __shfl_xor_sync(0xffffffffu, acc[s][m], 1);
                acc[s][m] += __shfl_xor_sync(0xffffffffu, acc[s][m], 2);
            }
        }

        // ng=1 publishes partials
        if (ng == 1 && c == 0) {
            float* p = ped + (o & 1) * 384 + (eg * 8 + r) * 12;
            #pragma unroll
            for (int s = 0; s < 4; s++) {
                p[s*3+0] = acc[s][0]; p[s*3+1] = acc[s][1]; p[s*3+2] = acc[s][2];
            }
        }

        // stage next buffer
        if (o + 1 < NCHUNK) {
            float4* d = (float4*)(smem + SM_B + ((o + 1) & 1) * 24576);
            #pragma unroll
            for (int j = 0; j < 6; j++) d[tid + j * 256] = stg[j];
        }
        __syncthreads();

        // ng=0 combines + stores
        if (ng == 0 && c == 0) {
            const float* p = ped + (o & 1) * 384 + (eg * 8 + r) * 12;
            #pragma unroll
            for (int s = 0; s < 4; s++) {
                float* op = out + (size_t)(E0 + ebase + 8*s) * (NCOUT * MO) + o * 3;
                op[0] = acc[s][0] + p[s*3+0];
                op[1] = acc[s][1] + p[s*3+1];
                op[2] = acc[s][2] + p[s*3+2];
            }
        }
    }
}

// ---------------- launch ----------------
extern "C" void kernel_launch(void* const* d_in, const int* in_sizes, int n_in,
                              void* d_out, int out_size) {
    const float* edges = (const float*)d_in[0];
    const float* feats = (const float*)d_in[1];
    const float* basis = (const float*)d_in[2];
    const float* W1    = (const float*)d_in[3];
    const float* b1    = (const float*)d_in[4];
    const float* g1    = (const float*)d_in[5];
    const float* be1   = (const float*)d_in[6];
    const float* W2    = (const float*)d_in[7];
    const float* b2    = (const float*)d_in[8];
    const float* g2    = (const float*)d_in[9];
    const float* be2   = (const float*)d_in[10];
    const float* W3    = (const float*)d_in[11];
    float* out = (float*)d_out;

    const int E = in_sizes[0] / EDGE_DIM;

    prep_w3<<<(MID * RADW + 255) / 256, 256>>>(W3);
    mlp_kernel<<<(E + 63) / 64, 256>>>(edges, W1, b1, g1, be1, W2, b2, g2, be2, E);

    cudaFuncSetAttribute(pair_main_kernel,
                         cudaFuncAttributeMaxDynamicSharedMemorySize, SM_TOTAL);
    pair_main_kernel<<<E / 128, 256, SM_TOTAL>>>(feats, basis, out, E);
}

// round 7
// speedup vs baseline: 5.6325x; 1.1708x over previous
#include <cuda_runtime.h>
#include <cuda_fp16.h>
#include <cstdint>

// ---------------- problem constants ----------------
#define EDGE_DIM 32
#define MID      64
#define NCIN     32
#define NCOUT    32
#define MO       3
#define QDIM     96
#define RADW     3072
#define EMAX     32768
#define NCHUNK   32

// scratch
__device__ float  g_h[EMAX * MID];
// per chunk 12288 B: [ng(2)][j(12)][lane(32) x 16B] fragment-register-order (hi only)
__device__ __half g_B[NCHUNK * 12288 / 2];

// ---------------- helpers ----------------
__device__ __forceinline__ float gelu_exact(float x) {
    return 0.5f * x * (1.0f + erff(x * 0.70710678118654752440f));
}
__device__ __forceinline__ float warp_allreduce_sum(float v) {
    v += __shfl_xor_sync(0xffffffffu, v, 16);
    v += __shfl_xor_sync(0xffffffffu, v, 8);
    v += __shfl_xor_sync(0xffffffffu, v, 4);
    v += __shfl_xor_sync(0xffffffffu, v, 2);
    v += __shfl_xor_sync(0xffffffffu, v, 1);
    return v;
}
__device__ __forceinline__ void split2(float2 p, uint32_t& hi, uint32_t& lo) {
    __half h0 = __float2half_rn(p.x), h1 = __float2half_rn(p.y);
    float  r0 = p.x - __half2float(h0), r1 = p.y - __half2float(h1);
    __half l0 = __float2half_rn(r0), l1 = __float2half_rn(r1);
    __half2 hh = __halves2half2(h0, h1), ll = __halves2half2(l0, l1);
    hi = *(uint32_t*)&hh;
    lo = *(uint32_t*)&ll;
}
__device__ __forceinline__ void mma16816(float c[4], const uint32_t a[4],
                                         uint32_t b0, uint32_t b1) {
    asm volatile(
        "mma.sync.aligned.m16n8k16.row.col.f32.f16.f16.f32 "
        "{%0,%1,%2,%3}, {%4,%5,%6,%7}, {%8,%9}, {%0,%1,%2,%3};"
        : "+f"(c[0]), "+f"(c[1]), "+f"(c[2]), "+f"(c[3])
        : "r"(a[0]), "r"(a[1]), "r"(a[2]), "r"(a[3]), "r"(b0), "r"(b1));
}

// ---------------- Kernel P: W3 -> fragment-register-order fp16 image (hi only) ----
__global__ void __launch_bounds__(256) prep_w3(const float* __restrict__ W3) {
    int idx = blockIdx.x * 256 + threadIdx.x;     // over 64*3072
    if (idx >= MID * RADW) return;
    int k = idx / RADW, n = idx % RADW;
    int chunk = n / QDIM, nl = n % QDIM;
    int ng = nl / 48, nq = nl % 48;
    int nt = nq >> 3, rr = nq & 7;
    int kt = k >> 4, kk = k & 15;
    int cc = (kk >> 1) & 3, bb = kk >> 3, hp = kk & 1;
    int lane = rr * 4 + cc;
    int j = kt * 3 + (nt >> 1);
    int r4 = ((nt & 1) << 1) + bb;
    int off = chunk * 12288 + ng * 6144 + j * 512 + lane * 16 + r4 * 4 + hp * 2;
    g_B[off >> 1] = __float2half_rn(W3[idx]);
}

// ---------------- Kernel A: radial MLP (known-good) ----------------
__global__ void __launch_bounds__(256) mlp_kernel(
    const float* __restrict__ edges,
    const float* __restrict__ W1, const float* __restrict__ b1,
    const float* __restrict__ g1, const float* __restrict__ be1,
    const float* __restrict__ W2, const float* __restrict__ b2,
    const float* __restrict__ g2, const float* __restrict__ be2,
    int E)
{
    __shared__ float W1s[EDGE_DIM * MID];
    __shared__ float W2s[MID * MID];
    __shared__ float prm[6 * MID];
    const int tid = threadIdx.x;
    for (int i = tid; i < EDGE_DIM * MID; i += 256) W1s[i] = W1[i];
    for (int i = tid; i < MID * MID; i += 256)      W2s[i] = W2[i];
    if (tid < MID) {
        prm[tid] = b1[tid]; prm[MID + tid] = g1[tid]; prm[2*MID + tid] = be1[tid];
        prm[3*MID + tid] = b2[tid]; prm[4*MID + tid] = g2[tid]; prm[5*MID + tid] = be2[tid];
    }
    __syncthreads();
    const int warp = tid >> 5, lane = tid & 31;
    for (int it = 0; it < 8; it++) {
        const int e = blockIdx.x * 64 + warp * 8 + it;
        if (e >= E) break;
        const float xv = edges[e * EDGE_DIM + lane];
        float a0 = prm[lane], a1 = prm[lane + 32];
        #pragma unroll
        for (int k = 0; k < 32; k++) {
            const float xk = __shfl_sync(0xffffffffu, xv, k);
            a0 = fmaf(xk, W1s[k * MID + lane], a0);
            a1 = fmaf(xk, W1s[k * MID + lane + 32], a1);
        }
        float mean = warp_allreduce_sum(a0 + a1) * (1.0f / 64.0f);
        float d0 = a0 - mean, d1 = a1 - mean;
        float var = warp_allreduce_sum(d0 * d0 + d1 * d1) * (1.0f / 64.0f);
        float inv = rsqrtf(var + 1e-5f);
        a0 = gelu_exact(d0 * inv * prm[MID + lane]      + prm[2*MID + lane]);
        a1 = gelu_exact(d1 * inv * prm[MID + lane + 32] + prm[2*MID + lane + 32]);
        float c0 = prm[3*MID + lane], c1 = prm[3*MID + lane + 32];
        #pragma unroll
        for (int k = 0; k < 32; k++) {
            const float u = __shfl_sync(0xffffffffu, a0, k);
            const float w = __shfl_sync(0xffffffffu, a1, k);
            c0 = fmaf(u, W2s[k * MID + lane], c0);
            c0 = fmaf(w, W2s[(k + 32) * MID + lane], c0);
            c1 = fmaf(u, W2s[k * MID + lane + 32], c1);
            c1 = fmaf(w, W2s[(k + 32) * MID + lane + 32], c1);
        }
        mean = warp_allreduce_sum(c0 + c1) * (1.0f / 64.0f);
        d0 = c0 - mean; d1 = c1 - mean;
        var = warp_allreduce_sum(d0 * d0 + d1 * d1) * (1.0f / 64.0f);
        inv = rsqrtf(var + 1e-5f);
        c0 = gelu_exact(d0 * inv * prm[4*MID + lane]      + prm[5*MID + lane]);
        c1 = gelu_exact(d1 * inv * prm[4*MID + lane + 32] + prm[5*MID + lane + 32]);
        g_h[e * MID + lane]      = c0;
        g_h[e * MID + lane + 32] = c1;
    }
}

// ---------------- Kernel M: mma.sync fp16 2-pass, warp = 32 edges x 48 n ----------------
// 256 thr / 8 warps = 4 edge-groups x 2 n-halves; 128 edges per CTA.
#define SM_B     0                         // 2 x 12288
#define SM_T     24576                     // 128 edges x 832 B
#define SM_PED   (24576 + 128*832)         // 2 parity x 4 eg x 8 r x 12 floats
#define SM_TOTAL (SM_PED + 3072)           // 134144

__global__ void __launch_bounds__(256, 1) pair_main_kernel(
    const float* __restrict__ feats,
    const float* __restrict__ basis,
    float* __restrict__ out,
    int E)
{
    extern __shared__ __align__(1024) char smem[];
    const int tid = threadIdx.x, w = tid >> 5, lane = tid & 31;
    const int r = lane >> 2, c = lane & 3;
    const int eg = w >> 1, ng = w & 1;
    const int E0 = blockIdx.x * 128;
    const int ebase = eg * 32 + r;

    // ---- A fragments: fp16 hi/lo, resident in registers ----
    uint32_t Ahi[2][4][4], Alo[2][4][4];
    #pragma unroll
    for (int mt = 0; mt < 2; mt++) {
        const size_t e0 = (size_t)(E0 + ebase + mt * 16) * MID;
        const size_t e1 = e0 + 8 * MID;
        #pragma unroll
        for (int kt = 0; kt < 4; kt++) {
            const int k0 = kt * 16 + 2 * c;
            float2 p0 = *(const float2*)(g_h + e0 + k0);
            float2 p1 = *(const float2*)(g_h + e0 + k0 + 8);
            float2 p2 = *(const float2*)(g_h + e1 + k0);
            float2 p3 = *(const float2*)(g_h + e1 + k0 + 8);
            split2(p0, Ahi[mt][kt][0], Alo[mt][kt][0]);
            split2(p2, Ahi[mt][kt][1], Alo[mt][kt][1]);
            split2(p1, Ahi[mt][kt][2], Alo[mt][kt][2]);
            split2(p3, Ahi[mt][kt][3], Alo[mt][kt][3]);
        }
    }

    // ---- T tile: per (e, qp) one uint4 = fp16 {t0[0],t0[1], t0[2],_, t1[0],t1[1], t1[2],_}
    for (int idx = tid; idx < 128 * 48; idx += 256) {
        const int e = idx / 48, qp = idx % 48;
        const int q0 = 2 * qp, q1 = q0 + 1;
        const int i0 = q0 / 3, f0 = q0 % 3, i1 = q1 / 3, f1 = q1 % 3;
        const float* fe = feats + (size_t)(E0 + e) * (NCIN * 3);
        const float* be = basis + (size_t)(E0 + e) * 27;
        const float a0 = fe[i0*3], a1 = fe[i0*3+1], a2 = fe[i0*3+2];
        const float b0 = fe[i1*3], b1 = fe[i1*3+1], b2 = fe[i1*3+2];
        float t0[3], t1[3];
        #pragma unroll
        for (int m = 0; m < 3; m++) {
            t0[m] = a0 * be[f0*3+m] + a1 * be[9 + f0*3+m] + a2 * be[18 + f0*3+m];
            t1[m] = b0 * be[f1*3+m] + b1 * be[9 + f1*3+m] + b2 * be[18 + f1*3+m];
        }
        half2 hx = __floats2half2_rn(t0[0], t0[1]);
        half2 hy = __floats2half2_rn(t0[2], 0.0f);
        half2 hz = __floats2half2_rn(t1[0], t1[1]);
        half2 hw = __floats2half2_rn(t1[2], 0.0f);
        uint4 v;
        v.x = *(uint32_t*)&hx; v.y = *(uint32_t*)&hy;
        v.z = *(uint32_t*)&hz; v.w = *(uint32_t*)&hw;
        *(uint4*)(smem + SM_T + e * 832 + qp * 16) = v;
    }

    // ---- stage chunk 0 (12288 B = 768 float4, 3 per thread) ----
    const float4* gB4 = (const float4*)g_B;
    {
        float4* d = (float4*)(smem + SM_B);
        #pragma unroll
        for (int j = 0; j < 3; j++) d[tid + j * 256] = gB4[tid + j * 256];
    }
    __syncthreads();

    float* ped = (float*)(smem + SM_PED);

    for (int o = 0; o < NCHUNK; o++) {
        // prefetch next chunk
        float4 stg[3];
        if (o + 1 < NCHUNK) {
            #pragma unroll
            for (int j = 0; j < 3; j++)
                stg[j] = gB4[(size_t)(o + 1) * 768 + tid + j * 256];
        }

        const char* buf = smem + SM_B + (o & 1) * 12288 + ng * 6144;
        float C[2][6][4];
        #pragma unroll
        for (int mt = 0; mt < 2; mt++)
            #pragma unroll
            for (int nt = 0; nt < 6; nt++) {
                C[mt][nt][0] = 0.f; C[mt][nt][1] = 0.f;
                C[mt][nt][2] = 0.f; C[mt][nt][3] = 0.f;
            }

        #pragma unroll
        for (int kt = 0; kt < 4; kt++) {
            uint4 bh[3];
            #pragma unroll
            for (int jj = 0; jj < 3; jj++)
                bh[jj] = *(const uint4*)(buf + (kt*3 + jj) * 512 + lane * 16);
            #pragma unroll
            for (int jj = 0; jj < 3; jj++) {
                #pragma unroll
                for (int mt = 0; mt < 2; mt++) {
                    mma16816(C[mt][2*jj],   Ahi[mt][kt], bh[jj].x, bh[jj].y);
                    mma16816(C[mt][2*jj],   Alo[mt][kt], bh[jj].x, bh[jj].y);
                    mma16816(C[mt][2*jj+1], Ahi[mt][kt], bh[jj].z, bh[jj].w);
                    mma16816(C[mt][2*jj+1], Alo[mt][kt], bh[jj].z, bh[jj].w);
                }
            }
        }

        // ---- epilogue ----
        float acc[4][3];
        #pragma unroll
        for (int s = 0; s < 4; s++) { acc[s][0]=0.f; acc[s][1]=0.f; acc[s][2]=0.f; }

        #pragma unroll
        for (int nt = 0; nt < 6; nt++) {
            const int qp = ng * 24 + nt * 4 + c;
            #pragma unroll
            for (int s = 0; s < 4; s++) {
                const int es = ebase + 8 * s;
                uint4 tv = *(const uint4*)(smem + SM_T + es * 832 + qp * 16);
                float2 u0 = __half22float2(*(half2*)&tv.x);
                float2 u1 = __half22float2(*(half2*)&tv.y);
                float2 u2 = __half22float2(*(half2*)&tv.z);
                float2 u3 = __half22float2(*(half2*)&tv.w);
                const float cA = C[s >> 1][nt][(s & 1) * 2];
                const float cB = C[s >> 1][nt][(s & 1) * 2 + 1];
                acc[s][0] = fmaf(cA, u0.x, fmaf(cB, u2.x, acc[s][0]));
                acc[s][1] = fmaf(cA, u0.y, fmaf(cB, u2.y, acc[s][1]));
                acc[s][2] = fmaf(cA, u1.x, fmaf(cB, u3.x, acc[s][2]));
            }
        }
        #pragma unroll
        for (int s = 0; s < 4; s++) {
            #pragma unroll
            for (int m = 0; m < 3; m++) {
                acc[s][m] += __shfl_xor_sync(0xffffffffu, acc[s][m], 1);
                acc[s][m] += __shfl_xor_sync(0xffffffffu, acc[s][m], 2);
            }
        }

        // ng=1 publishes partials
        if (ng == 1 && c == 0) {
            float* p = ped + (o & 1) * 384 + (eg * 8 + r) * 12;
            #pragma unroll
            for (int s = 0; s < 4; s++) {
                p[s*3+0] = acc[s][0]; p[s*3+1] = acc[s][1]; p[s*3+2] = acc[s][2];
            }
        }

        // stage next buffer
        if (o + 1 < NCHUNK) {
            float4* d = (float4*)(smem + SM_B + ((o + 1) & 1) * 12288);
            #pragma unroll
            for (int j = 0; j < 3; j++) d[tid + j * 256] = stg[j];
        }
        __syncthreads();

        // ng=0 combines + stores
        if (ng == 0 && c == 0) {
            const float* p = ped + (o & 1) * 384 + (eg * 8 + r) * 12;
            #pragma unroll
            for (int s = 0; s < 4; s++) {
                float* op = out + (size_t)(E0 + ebase + 8*s) * (NCOUT * MO) + o * 3;
                op[0] = acc[s][0] + p[s*3+0];
                op[1] = acc[s][1] + p[s*3+1];
                op[2] = acc[s][2] + p[s*3+2];
            }
        }
    }
}

// ---------------- launch ----------------
extern "C" void kernel_launch(void* const* d_in, const int* in_sizes, int n_in,
                              void* d_out, int out_size) {
    const float* edges = (const float*)d_in[0];
    const float* feats = (const float*)d_in[1];
    const float* basis = (const float*)d_in[2];
    const float* W1    = (const float*)d_in[3];
    const float* b1    = (const float*)d_in[4];
    const float* g1    = (const float*)d_in[5];
    const float* be1   = (const float*)d_in[6];
    const float* W2    = (const float*)d_in[7];
    const float* b2    = (const float*)d_in[8];
    const float* g2    = (const float*)d_in[9];
    const float* be2   = (const float*)d_in[10];
    const float* W3    = (const float*)d_in[11];
    float* out = (float*)d_out;

    const int E = in_sizes[0] / EDGE_DIM;

    prep_w3<<<(MID * RADW + 255) / 256, 256>>>(W3);
    mlp_kernel<<<(E + 63) / 64, 256>>>(edges, W1, b1, g1, be1, W2, b2, g2, be2, E);

    cudaFuncSetAttribute(pair_main_kernel,
                         cudaFuncAttributeMaxDynamicSharedMemorySize, SM_TOTAL);
    pair_main_kernel<<<E / 128, 256, SM_TOTAL>>>(feats, basis, out, E);
}

// round 8
// speedup vs baseline: 6.5580x; 1.1643x over previous
#include <cuda_runtime.h>
#include <cuda_fp16.h>
#include <cstdint>

// ---------------- problem constants ----------------
#define EDGE_DIM 32
#define MID      64
#define NCIN     32
#define NCOUT    32
#define MO       3
#define QDIM     96
#define RADW     3072
#define EMAX     32768
#define NCHUNK   32

// scratch
__device__ float  g_h[EMAX * MID];
// per chunk 12288 B: [ng(2)][j(12)][lane(32) x 16B] fragment-register-order (hi only)
__device__ __half g_B[NCHUNK * 12288 / 2];

// ---------------- helpers ----------------
__device__ __forceinline__ float gelu_exact(float x) {
    return 0.5f * x * (1.0f + erff(x * 0.70710678118654752440f));
}
__device__ __forceinline__ float warp_allreduce_sum(float v) {
    v += __shfl_xor_sync(0xffffffffu, v, 16);
    v += __shfl_xor_sync(0xffffffffu, v, 8);
    v += __shfl_xor_sync(0xffffffffu, v, 4);
    v += __shfl_xor_sync(0xffffffffu, v, 2);
    v += __shfl_xor_sync(0xffffffffu, v, 1);
    return v;
}
__device__ __forceinline__ uint32_t pack_h2(float x, float y) {
    half2 h = __floats2half2_rn(x, y);
    return *(uint32_t*)&h;
}
__device__ __forceinline__ void mma16816(float c[4], const uint32_t a[4],
                                         uint32_t b0, uint32_t b1) {
    asm volatile(
        "mma.sync.aligned.m16n8k16.row.col.f32.f16.f16.f32 "
        "{%0,%1,%2,%3}, {%4,%5,%6,%7}, {%8,%9}, {%0,%1,%2,%3};"
        : "+f"(c[0]), "+f"(c[1]), "+f"(c[2]), "+f"(c[3])
        : "r"(a[0]), "r"(a[1]), "r"(a[2]), "r"(a[3]), "r"(b0), "r"(b1));
}

// ---------------- Kernel P: W3 -> fragment-register-order fp16 image ----------
__global__ void __launch_bounds__(256) prep_w3(const float* __restrict__ W3) {
    int idx = blockIdx.x * 256 + threadIdx.x;     // over 64*3072
    if (idx >= MID * RADW) return;
    int k = idx / RADW, n = idx % RADW;
    int chunk = n / QDIM, nl = n % QDIM;
    int ng = nl / 48, nq = nl % 48;
    int nt = nq >> 3, rr = nq & 7;
    int kt = k >> 4, kk = k & 15;
    int cc = (kk >> 1) & 3, bb = kk >> 3, hp = kk & 1;
    int lane = rr * 4 + cc;
    int j = kt * 3 + (nt >> 1);
    int r4 = ((nt & 1) << 1) + bb;
    int off = chunk * 12288 + ng * 6144 + j * 512 + lane * 16 + r4 * 4 + hp * 2;
    g_B[off >> 1] = __float2half_rn(W3[idx]);
}

// ---------------- Kernel A: radial MLP (known-good) ----------------
__global__ void __launch_bounds__(256) mlp_kernel(
    const float* __restrict__ edges,
    const float* __restrict__ W1, const float* __restrict__ b1,
    const float* __restrict__ g1, const float* __restrict__ be1,
    const float* __restrict__ W2, const float* __restrict__ b2,
    const float* __restrict__ g2, const float* __restrict__ be2,
    int E)
{
    __shared__ float W1s[EDGE_DIM * MID];
    __shared__ float W2s[MID * MID];
    __shared__ float prm[6 * MID];
    const int tid = threadIdx.x;
    for (int i = tid; i < EDGE_DIM * MID; i += 256) W1s[i] = W1[i];
    for (int i = tid; i < MID * MID; i += 256)      W2s[i] = W2[i];
    if (tid < MID) {
        prm[tid] = b1[tid]; prm[MID + tid] = g1[tid]; prm[2*MID + tid] = be1[tid];
        prm[3*MID + tid] = b2[tid]; prm[4*MID + tid] = g2[tid]; prm[5*MID + tid] = be2[tid];
    }
    __syncthreads();
    const int warp = tid >> 5, lane = tid & 31;
    for (int it = 0; it < 8; it++) {
        const int e = blockIdx.x * 64 + warp * 8 + it;
        if (e >= E) break;
        const float xv = edges[e * EDGE_DIM + lane];
        float a0 = prm[lane], a1 = prm[lane + 32];
        #pragma unroll
        for (int k = 0; k < 32; k++) {
            const float xk = __shfl_sync(0xffffffffu, xv, k);
            a0 = fmaf(xk, W1s[k * MID + lane], a0);
            a1 = fmaf(xk, W1s[k * MID + lane + 32], a1);
        }
        float mean = warp_allreduce_sum(a0 + a1) * (1.0f / 64.0f);
        float d0 = a0 - mean, d1 = a1 - mean;
        float var = warp_allreduce_sum(d0 * d0 + d1 * d1) * (1.0f / 64.0f);
        float inv = rsqrtf(var + 1e-5f);
        a0 = gelu_exact(d0 * inv * prm[MID + lane]      + prm[2*MID + lane]);
        a1 = gelu_exact(d1 * inv * prm[MID + lane + 32] + prm[2*MID + lane + 32]);
        float c0 = prm[3*MID + lane], c1 = prm[3*MID + lane + 32];
        #pragma unroll
        for (int k = 0; k < 32; k++) {
            const float u = __shfl_sync(0xffffffffu, a0, k);
            const float w = __shfl_sync(0xffffffffu, a1, k);
            c0 = fmaf(u, W2s[k * MID + lane], c0);
            c0 = fmaf(w, W2s[(k + 32) * MID + lane], c0);
            c1 = fmaf(u, W2s[k * MID + lane + 32], c1);
            c1 = fmaf(w, W2s[(k + 32) * MID + lane + 32], c1);
        }
        mean = warp_allreduce_sum(c0 + c1) * (1.0f / 64.0f);
        d0 = c0 - mean; d1 = c1 - mean;
        var = warp_allreduce_sum(d0 * d0 + d1 * d1) * (1.0f / 64.0f);
        inv = rsqrtf(var + 1e-5f);
        c0 = gelu_exact(d0 * inv * prm[4*MID + lane]      + prm[5*MID + lane]);
        c1 = gelu_exact(d1 * inv * prm[4*MID + lane + 32] + prm[5*MID + lane + 32]);
        g_h[e * MID + lane]      = c0;
        g_h[e * MID + lane + 32] = c1;
    }
}

// ---------------- Kernel M: mma.sync fp16 1-pass, warp = 32 edges x 48 n ----------------
// 256 thr / 8 warps = 4 edge-groups x 2 n-halves; 128 edges per CTA.
#define SM_B     0                         // 2 x 12288
#define SM_T     24576                     // 128 edges x 832 B
#define SM_PED   (24576 + 128*832)         // 2 parity x 4 eg x 8 r x 12 floats
#define SM_TOTAL (SM_PED + 3072)           // 134144

__global__ void __launch_bounds__(256, 1) pair_main_kernel(
    const float* __restrict__ feats,
    const float* __restrict__ basis,
    float* __restrict__ out,
    int E)
{
    extern __shared__ __align__(1024) char smem[];
    const int tid = threadIdx.x, w = tid >> 5, lane = tid & 31;
    const int r = lane >> 2, c = lane & 3;
    const int eg = w >> 1, ng = w & 1;
    const int E0 = blockIdx.x * 128;
    const int ebase = eg * 32 + r;

    // ---- A fragments: fp16, resident in registers ----
    uint32_t A[2][4][4];
    #pragma unroll
    for (int mt = 0; mt < 2; mt++) {
        const size_t e0 = (size_t)(E0 + ebase + mt * 16) * MID;
        const size_t e1 = e0 + 8 * MID;
        #pragma unroll
        for (int kt = 0; kt < 4; kt++) {
            const int k0 = kt * 16 + 2 * c;
            float2 p0 = *(const float2*)(g_h + e0 + k0);
            float2 p1 = *(const float2*)(g_h + e0 + k0 + 8);
            float2 p2 = *(const float2*)(g_h + e1 + k0);
            float2 p3 = *(const float2*)(g_h + e1 + k0 + 8);
            A[mt][kt][0] = pack_h2(p0.x, p0.y);
            A[mt][kt][1] = pack_h2(p2.x, p2.y);
            A[mt][kt][2] = pack_h2(p1.x, p1.y);
            A[mt][kt][3] = pack_h2(p3.x, p3.y);
        }
    }

    // ---- T tile: per (e, qp) one uint4 = fp16 {t0[0],t0[1], t0[2],_, t1[0],t1[1], t1[2],_}
    for (int idx = tid; idx < 128 * 48; idx += 256) {
        const int e = idx / 48, qp = idx % 48;
        const int q0 = 2 * qp, q1 = q0 + 1;
        const int i0 = q0 / 3, f0 = q0 % 3, i1 = q1 / 3, f1 = q1 % 3;
        const float* fe = feats + (size_t)(E0 + e) * (NCIN * 3);
        const float* be = basis + (size_t)(E0 + e) * 27;
        const float a0 = fe[i0*3], a1 = fe[i0*3+1], a2 = fe[i0*3+2];
        const float b0 = fe[i1*3], b1 = fe[i1*3+1], b2 = fe[i1*3+2];
        float t0[3], t1[3];
        #pragma unroll
        for (int m = 0; m < 3; m++) {
            t0[m] = a0 * be[f0*3+m] + a1 * be[9 + f0*3+m] + a2 * be[18 + f0*3+m];
            t1[m] = b0 * be[f1*3+m] + b1 * be[9 + f1*3+m] + b2 * be[18 + f1*3+m];
        }
        uint4 v;
        v.x = pack_h2(t0[0], t0[1]);
        v.y = pack_h2(t0[2], 0.0f);
        v.z = pack_h2(t1[0], t1[1]);
        v.w = pack_h2(t1[2], 0.0f);
        *(uint4*)(smem + SM_T + e * 832 + qp * 16) = v;
    }

    // ---- stage chunk 0 (12288 B = 768 float4, 3 per thread) ----
    const float4* gB4 = (const float4*)g_B;
    {
        float4* d = (float4*)(smem + SM_B);
        #pragma unroll
        for (int j = 0; j < 3; j++) d[tid + j * 256] = gB4[tid + j * 256];
    }
    __syncthreads();

    float* ped = (float*)(smem + SM_PED);

    for (int o = 0; o < NCHUNK; o++) {
        // prefetch next chunk
        float4 stg[3];
        if (o + 1 < NCHUNK) {
            #pragma unroll
            for (int j = 0; j < 3; j++)
                stg[j] = gB4[(size_t)(o + 1) * 768 + tid + j * 256];
        }

        const char* buf = smem + SM_B + (o & 1) * 12288 + ng * 6144;
        float C[2][6][4];
        #pragma unroll
        for (int mt = 0; mt < 2; mt++)
            #pragma unroll
            for (int nt = 0; nt < 6; nt++) {
                C[mt][nt][0] = 0.f; C[mt][nt][1] = 0.f;
                C[mt][nt][2] = 0.f; C[mt][nt][3] = 0.f;
            }

        #pragma unroll
        for (int kt = 0; kt < 4; kt++) {
            uint4 bh[3];
            #pragma unroll
            for (int jj = 0; jj < 3; jj++)
                bh[jj] = *(const uint4*)(buf + (kt*3 + jj) * 512 + lane * 16);
            #pragma unroll
            for (int jj = 0; jj < 3; jj++) {
                #pragma unroll
                for (int mt = 0; mt < 2; mt++) {
                    mma16816(C[mt][2*jj],   A[mt][kt], bh[jj].x, bh[jj].y);
                    mma16816(C[mt][2*jj+1], A[mt][kt], bh[jj].z, bh[jj].w);
                }
            }
        }

        // ---- epilogue ----
        float acc[4][3];
        #pragma unroll
        for (int s = 0; s < 4; s++) { acc[s][0]=0.f; acc[s][1]=0.f; acc[s][2]=0.f; }

        #pragma unroll
        for (int nt = 0; nt < 6; nt++) {
            const int qp = ng * 24 + nt * 4 + c;
            #pragma unroll
            for (int s = 0; s < 4; s++) {
                const int es = ebase + 8 * s;
                uint4 tv = *(const uint4*)(smem + SM_T + es * 832 + qp * 16);
                float2 u0 = __half22float2(*(half2*)&tv.x);
                float2 u1 = __half22float2(*(half2*)&tv.y);
                float2 u2 = __half22float2(*(half2*)&tv.z);
                float2 u3 = __half22float2(*(half2*)&tv.w);
                const float cA = C[s >> 1][nt][(s & 1) * 2];
                const float cB = C[s >> 1][nt][(s & 1) * 2 + 1];
                acc[s][0] = fmaf(cA, u0.x, fmaf(cB, u2.x, acc[s][0]));
                acc[s][1] = fmaf(cA, u0.y, fmaf(cB, u2.y, acc[s][1]));
                acc[s][2] = fmaf(cA, u1.x, fmaf(cB, u3.x, acc[s][2]));
            }
        }
        #pragma unroll
        for (int s = 0; s < 4; s++) {
            #pragma unroll
            for (int m = 0; m < 3; m++) {
                acc[s][m] += __shfl_xor_sync(0xffffffffu, acc[s][m], 1);
                acc[s][m] += __shfl_xor_sync(0xffffffffu, acc[s][m], 2);
            }
        }

        // ng=1 publishes partials
        if (ng == 1 && c == 0) {
            float* p = ped + (o & 1) * 384 + (eg * 8 + r) * 12;
            #pragma unroll
            for (int s = 0; s < 4; s++) {
                p[s*3+0] = acc[s][0]; p[s*3+1] = acc[s][1]; p[s*3+2] = acc[s][2];
            }
        }

        // stage next buffer
        if (o + 1 < NCHUNK) {
            float4* d = (float4*)(smem + SM_B + ((o + 1) & 1) * 12288);
            #pragma unroll
            for (int j = 0; j < 3; j++) d[tid + j * 256] = stg[j];
        }
        __syncthreads();

        // ng=0 combines + stores
        if (ng == 0 && c == 0) {
            const float* p = ped + (o & 1) * 384 + (eg * 8 + r) * 12;
            #pragma unroll
            for (int s = 0; s < 4; s++) {
                float* op = out + (size_t)(E0 + ebase + 8*s) * (NCOUT * MO) + o * 3;
                op[0] = acc[s][0] + p[s*3+0];
                op[1] = acc[s][1] + p[s*3+1];
                op[2] = acc[s][2] + p[s*3+2];
            }
        }
    }
}

// ---------------- launch ----------------
extern "C" void kernel_launch(void* const* d_in, const int* in_sizes, int n_in,
                              void* d_out, int out_size) {
    const float* edges = (const float*)d_in[0];
    const float* feats = (const float*)d_in[1];
    const float* basis = (const float*)d_in[2];
    const float* W1    = (const float*)d_in[3];
    const float* b1    = (const float*)d_in[4];
    const float* g1    = (const float*)d_in[5];
    const float* be1   = (const float*)d_in[6];
    const float* W2    = (const float*)d_in[7];
    const float* b2    = (const float*)d_in[8];
    const float* g2    = (const float*)d_in[9];
    const float* be2   = (const float*)d_in[10];
    const float* W3    = (const float*)d_in[11];
    float* out = (float*)d_out;

    const int E = in_sizes[0] / EDGE_DIM;

    prep_w3<<<(MID * RADW + 255) / 256, 256>>>(W3);
    mlp_kernel<<<(E + 63) / 64, 256>>>(edges, W1, b1, g1, be1, W2, b2, g2, be2, E);

    cudaFuncSetAttribute(pair_main_kernel,
                         cudaFuncAttributeMaxDynamicSharedMemorySize, SM_TOTAL);
    pair_main_kernel<<<E / 128, 256, SM_TOTAL>>>(feats, basis, out, E);
}